// round 10
// baseline (speedup 1.0000x reference)
#include <cuda_runtime.h>
#include <cuda_pipeline.h>
#include <cstdint>

#define NN 1000
#define D 128
#define STR 384      // K_att/V_att innermost stride in floats (3 * 128)
#define NW 8         // warps per CTA
#define CHN 24       // nodes per CTA-cooperative chunk (layers 0/1; 24 KB burst)
#define PWN 3        // nodes per warp per chunk (CHN / NW)
#define CHN2 48      // nodes per chunk (layer 2, K-only; 24 KB burst)
#define PWN2 6

__device__ __forceinline__ float4 zero4() { return make_float4(0.f, 0.f, 0.f, 0.f); }

// One CTA per batch, 8 warps, occupancy 4 (single wave of 512 CTAs).
// LOCKSTEP COOPERATIVE BURSTS: each iteration, all 8 warps together issue
// cp.async for 24 CONTIGUOUS compact nodes within a few cycles (24KB
// time-correlated burst at the memory controller), double-buffered; each
// warp then computes the 3 nodes it loaded. A per-iteration __syncthreads
// keeps warps phase-locked so bursts stay correlated for the whole kernel.

__global__ __launch_bounds__(256, 4)
void decoder_fused_kernel(
    const float* __restrict__ query,
    const float* __restrict__ K_att,
    const float* __restrict__ V_att,
    const int* __restrict__ mask,          // bool serialized as int32
    const float* __restrict__ W0_w,
    const float* __restrict__ W0_b,
    const float* __restrict__ Wq_w,
    const float* __restrict__ Wq_b,
    float* __restrict__ out)
{
    __shared__ __align__(16) float ring[2 * CHN * 256];   // 48 KB (2 bufs x 24 nodes x 1KB)
    __shared__ int nlist[NN];
    __shared__ __align__(16) float qs[D];
    __shared__ __align__(16) float mo[D];
    __shared__ float M2s, L2s;
    __shared__ int cnt_s;

    // merge scratch aliased onto ring (only used after pipeline drained + sync)
    float*  m_s = ring;                   // [NW][32]
    float*  l_s = ring + 256;             // [NW][32]
    float4* a_s = (float4*)(ring + 512);  // [NW][32]

    const int b = blockIdx.x;
    const int tid = threadIdx.x;
    const int wid = tid >> 5;
    const int lane = tid & 31;
    const int loff = 4 * lane;
    const float NEG = __int_as_float(0xff800000);  // -inf

    if (tid < D) qs[tid] = query[(size_t)b * D + tid];

    // ---- Compact unmasked node list (warp 0) ----
    const int* mrow = mask + (size_t)b * NN;
    if (wid == 0) {
        int base = 0;
        for (int start = 0; start < NN; start += 32) {
            int n = start + lane;
            bool keep = (n < NN) && (mrow[n] == 0);
            unsigned bal = __ballot_sync(0xffffffffu, keep);
            if (keep) nlist[base + __popc(bal & ((1u << lane) - 1u))] = n;
            base += __popc(bal);
        }
        if (lane == 0) cnt_s = base;
    }
    __syncthreads();
    const int cnt = cnt_s;

    const float* Kb = K_att + (size_t)b * NN * STR;
    const float* Vb = V_att + (size_t)b * NN * STR;

    // ==================== Layers 0 and 1 ====================
    for (int l = 0; l < 2; ++l) {
        const int cbase = l * D + loff;
        const int nch = (cnt + CHN - 1) / CHN;

        // stage chunk c into buffer c&1: warp w loads nodes 24c+3w .. +2 (K first, then V)
        auto stage01 = [&](int c) {
            float* buf = ring + (c & 1) * (CHN * 256) + (3 * wid) * 256;
            const int gbase = c * CHN + 3 * wid;
            #pragma unroll
            for (int j = 0; j < PWN; ++j) {
                int i = gbase + j;
                int node = nlist[i < cnt ? i : 0];
                __pipeline_memcpy_async(buf + j * 256 + loff,
                                        Kb + (size_t)node * STR + cbase, 16);
            }
            #pragma unroll
            for (int j = 0; j < PWN; ++j) {
                int i = gbase + j;
                int node = nlist[i < cnt ? i : 0];
                __pipeline_memcpy_async(buf + j * 256 + 128 + loff,
                                        Vb + (size_t)node * STR + cbase, 16);
            }
            __pipeline_commit();
        };

        if (0 < nch) stage01(0);
        if (1 < nch) stage01(1);
        if (nch >= 1 && nch < 2) __pipeline_commit();  // keep group count aligned

        const float4 q4 = *(const float4*)(qs + loff);
        float m = -1e30f, lsum = 0.0f;
        float4 acc = zero4();

        for (int c = 0; c < nch; ++c) {
            __pipeline_wait_prior(1);
            __syncthreads();   // lockstep: all warps aligned before compute+next burst

            const float* buf = ring + (c & 1) * (CHN * 256) + (3 * wid) * 256;
            const int gbase = c * CHN + 3 * wid;

            #pragma unroll
            for (int j = 0; j < PWN; ++j) {
                const float4 k4 = *(const float4*)(buf + j * 256 + loff);
                const float4 v4 = *(const float4*)(buf + j * 256 + 128 + loff);
                float s = k4.x * q4.x + k4.y * q4.y + k4.z * q4.z + k4.w * q4.w;
                s += __shfl_xor_sync(0xffffffffu, s, 1);
                s += __shfl_xor_sync(0xffffffffu, s, 2);
                s = (gbase + j < cnt) ? s * 0.25f : NEG;  // 1/sqrt(16)

                const float mn = fmaxf(m, s);
                const float cc = __expf(m - mn);
                const float e = __expf(s - mn);     // 0 for padded slots
                lsum = lsum * cc + e;
                acc.x = acc.x * cc + e * v4.x;
                acc.y = acc.y * cc + e * v4.y;
                acc.z = acc.z * cc + e * v4.z;
                acc.w = acc.w * cc + e * v4.w;
                m = mn;
            }

            // refill consumed buffer with chunk c+2 (all warps issue together)
            if (c + 2 < nch) stage01(c + 2);
            else __pipeline_commit();
        }
        __pipeline_wait_prior(0);
        __syncthreads();   // ring now dead -> merge scratch

        m_s[wid * 32 + lane] = m;
        l_s[wid * 32 + lane] = lsum;
        a_s[wid * 32 + lane] = acc;
        __syncthreads();

        if (tid < 32) {
            float M = m_s[lane];
            #pragma unroll
            for (int w = 1; w < NW; ++w) M = fmaxf(M, m_s[w * 32 + lane]);
            float L = 0.f, ax = 0.f, ay = 0.f, az = 0.f, aw = 0.f;
            #pragma unroll
            for (int w = 0; w < NW; ++w) {
                const float cc = __expf(m_s[w * 32 + lane] - M);
                L += l_s[w * 32 + lane] * cc;
                const float4 a = a_s[w * 32 + lane];
                ax += a.x * cc; ay += a.y * cc; az += a.z * cc; aw += a.w * cc;
            }
            const float inv = 1.0f / L;
            mo[4 * lane + 0] = ax * inv;
            mo[4 * lane + 1] = ay * inv;
            mo[4 * lane + 2] = az * inv;
            mo[4 * lane + 3] = aw * inv;
        }
        __syncthreads();

        if (tid < D) {   // query = mha_out @ W0_w.T + W0_b
            const float* Wr = W0_w + tid * D;
            float a2 = W0_b[tid];
            #pragma unroll 8
            for (int d = 0; d < D; ++d) a2 = fmaf(mo[d], Wr[d], a2);
            qs[tid] = a2;
        }
        __syncthreads();
    }

    // ==================== Layer 2: q_final = q @ Wq.T + b; 1-head, clip=10 ====================
    if (tid < D) {
        const float* Wr = Wq_w + tid * D;
        float a2 = Wq_b[tid];
        #pragma unroll 8
        for (int d = 0; d < D; ++d) a2 = fmaf(qs[d], Wr[d], a2);
        mo[tid] = a2;
    }
    __syncthreads();

    {
        const int cbase = 2 * D + loff;
        const float4 q4 = *(const float4*)(mo + loff);
        float* orow = out + (size_t)b * NN;
        const int nch = (cnt + CHN2 - 1) / CHN2;

        auto stage2 = [&](int c) {
            float* buf = ring + (c & 1) * (CHN2 * 128) + (PWN2 * wid) * 128;
            const int gbase = c * CHN2 + PWN2 * wid;
            #pragma unroll
            for (int j = 0; j < PWN2; ++j) {
                int i = gbase + j;
                int node = nlist[i < cnt ? i : 0];
                __pipeline_memcpy_async(buf + j * 128 + loff,
                                        Kb + (size_t)node * STR + cbase, 16);
            }
            __pipeline_commit();
        };

        if (0 < nch) stage2(0);
        if (1 < nch) stage2(1);
        if (nch >= 1 && nch < 2) __pipeline_commit();

        float m = -1e30f, lsum = 0.0f;
        for (int c = 0; c < nch; ++c) {
            __pipeline_wait_prior(1);
            __syncthreads();

            const float* buf = ring + (c & 1) * (CHN2 * 128) + (PWN2 * wid) * 128;
            const int gbase = c * CHN2 + PWN2 * wid;

            #pragma unroll
            for (int j = 0; j < PWN2; ++j) {
                const int i = gbase + j;
                const float4 k4 = *(const float4*)(buf + j * 128 + loff);
                float s = k4.x * q4.x + k4.y * q4.y + k4.z * q4.z + k4.w * q4.w;
                #pragma unroll
                for (int d = 1; d < 32; d <<= 1)
                    s += __shfl_xor_sync(0xffffffffu, s, d);
                s *= 0.08838834764831845f;  // 1/sqrt(128)
                s = 10.0f * (1.0f - __fdividef(2.0f, __expf(2.0f * s) + 1.0f));  // 10*tanh
                if (i < cnt) {
                    if (lane == 0) orow[nlist[i]] = s;
                } else s = NEG;
                const float mn = fmaxf(m, s);
                lsum = lsum * __expf(m - mn) + __expf(s - mn);
                m = mn;
            }

            if (c + 2 < nch) stage2(c + 2);
            else __pipeline_commit();
        }
        __pipeline_wait_prior(0);
        __syncthreads();

        if (lane == 0) { m_s[wid * 32] = m; l_s[wid * 32] = lsum; }
        __syncthreads();
        if (tid == 0) {
            float M = m_s[0];
            #pragma unroll
            for (int w = 1; w < NW; ++w) M = fmaxf(M, m_s[w * 32]);
            float L = 0.f;
            #pragma unroll
            for (int w = 0; w < NW; ++w) L += l_s[w * 32] * __expf(m_s[w * 32] - M);
            M2s = M;
            L2s = 1.0f / L;
        }
        __syncthreads();

        const float M = M2s, Li = L2s;
        for (int n = tid; n < NN; n += 256) {
            float v = 0.0f;
            if (mrow[n] == 0) v = __expf(orow[n] - M) * Li;
            orow[n] = v;
        }
    }
}

extern "C" void kernel_launch(void* const* d_in, const int* in_sizes, int n_in,
                              void* d_out, int out_size) {
    const float* query = (const float*)d_in[0];
    const float* K_att = (const float*)d_in[1];
    const float* V_att = (const float*)d_in[2];
    const int*   mask  = (const int*)d_in[3];
    const float* W0_w  = (const float*)d_in[4];
    const float* W0_b  = (const float*)d_in[5];
    const float* Wq_w  = (const float*)d_in[6];
    const float* Wq_b  = (const float*)d_in[7];
    float* out = (float*)d_out;

    decoder_fused_kernel<<<512, 256>>>(query, K_att, V_att, mask,
                                       W0_w, W0_b, Wq_w, Wq_b, out);
}

// round 11
// speedup vs baseline: 1.0138x; 1.0138x over previous
#include <cuda_runtime.h>
#include <cuda_pipeline.h>
#include <cstdint>

#define NN 1000
#define D 128
#define STR 384      // K_att/V_att innermost stride in floats (3 * 128)
#define NW 8         // warps per CTA
#define CH 3         // adjacent nodes per chunk
#define DEPTH 2      // double buffer

__device__ __forceinline__ float4 zero4() { return make_float4(0.f, 0.f, 0.f, 0.f); }

// One CTA per batch, 8 warps, occupancy 4 (single wave of 512 CTAs).
// R8 winning config (round-robin CH=3 chunks, cp.async double buffer) plus:
//  - K copies grouped before V copies inside each chunk (1.5KB per-array runs)
//  - layer-2 logits staged in smem (no gmem round-trip in the epilogue)
//  - uint16 nlist to fit the occ-4 smem budget

__global__ __launch_bounds__(256, 4)
void decoder_fused_kernel(
    const float* __restrict__ query,
    const float* __restrict__ K_att,
    const float* __restrict__ V_att,
    const int* __restrict__ mask,          // bool serialized as int32
    const float* __restrict__ W0_w,
    const float* __restrict__ W0_b,
    const float* __restrict__ Wq_w,
    const float* __restrict__ Wq_b,
    float* __restrict__ out)
{
    __shared__ __align__(16) float ring[NW * DEPTH * CH * 256];  // 48 KB
    __shared__ unsigned short nlist[NN];                          // 2 KB
    __shared__ float ss[NN];                                      // 4 KB (staged logits)
    __shared__ __align__(16) float qs[D];
    __shared__ __align__(16) float mo[D];
    __shared__ float M2s, L2s;
    __shared__ int cnt_s;

    // merge scratch aliased onto ring (dead between layer loops)
    float*  m_s = ring;                   // [NW][32]
    float*  l_s = ring + 256;             // [NW][32]
    float4* a_s = (float4*)(ring + 512);  // [NW][32]

    const int b = blockIdx.x;
    const int tid = threadIdx.x;
    const int wid = tid >> 5;
    const int lane = tid & 31;
    const int loff = 4 * lane;
    const float NEG = __int_as_float(0xff800000);  // -inf

    if (tid < D) qs[tid] = query[(size_t)b * D + tid];

    // ---- Compact unmasked node list (warp 0) ----
    const int* mrow = mask + (size_t)b * NN;
    if (wid == 0) {
        int base = 0;
        for (int start = 0; start < NN; start += 32) {
            int n = start + lane;
            bool keep = (n < NN) && (mrow[n] == 0);
            unsigned bal = __ballot_sync(0xffffffffu, keep);
            if (keep) nlist[base + __popc(bal & ((1u << lane) - 1u))] = (unsigned short)n;
            base += __popc(bal);
        }
        if (lane == 0) cnt_s = base;
    }
    __syncthreads();
    const int cnt = cnt_s;
    const int nch = (cnt + CH - 1) / CH;

    const float* Kb = K_att + (size_t)b * NN * STR;
    const float* Vb = V_att + (size_t)b * NN * STR;
    float* rw = ring + wid * (DEPTH * CH * 256);

    // ==================== Layers 0 and 1 ====================
    for (int l = 0; l < 2; ++l) {
        const int cbase = l * D + loff;

        // prologue: fill both buffers (chunks w, w+NW); K runs first, then V runs
        #pragma unroll
        for (int d = 0; d < DEPTH; ++d) {
            const int c = wid + d * NW;
            float* buf = rw + d * (CH * 256);
            if (c < nch) {
                #pragma unroll
                for (int j = 0; j < CH; ++j) {
                    int i = c * CH + j;
                    int node = nlist[i < cnt ? i : 0];
                    __pipeline_memcpy_async(buf + j * 256 + loff,
                                            Kb + (size_t)node * STR + cbase, 16);
                }
                #pragma unroll
                for (int j = 0; j < CH; ++j) {
                    int i = c * CH + j;
                    int node = nlist[i < cnt ? i : 0];
                    __pipeline_memcpy_async(buf + j * 256 + 128 + loff,
                                            Vb + (size_t)node * STR + cbase, 16);
                }
            }
            __pipeline_commit();
        }

        const float4 q4 = *(const float4*)(qs + loff);
        float m = -1e30f, lsum = 0.0f;
        float4 acc = zero4();

        int it = 0;
        for (int c = wid; c < nch; c += NW, ++it) {
            __pipeline_wait_prior(1);
            float* buf = rw + (it & 1) * (CH * 256);

            #pragma unroll
            for (int j = 0; j < CH; ++j) {
                const float4 k4 = *(const float4*)(buf + j * 256 + loff);
                const float4 v4 = *(const float4*)(buf + j * 256 + 128 + loff);
                float s = k4.x * q4.x + k4.y * q4.y + k4.z * q4.z + k4.w * q4.w;
                s += __shfl_xor_sync(0xffffffffu, s, 1);
                s += __shfl_xor_sync(0xffffffffu, s, 2);
                s = (c * CH + j < cnt) ? s * 0.25f : NEG;  // 1/sqrt(16)

                const float mn = fmaxf(m, s);
                const float cc = __expf(m - mn);
                const float e = __expf(s - mn);     // 0 for padded slots
                lsum = lsum * cc + e;
                acc.x = acc.x * cc + e * v4.x;
                acc.y = acc.y * cc + e * v4.y;
                acc.z = acc.z * cc + e * v4.z;
                acc.w = acc.w * cc + e * v4.w;
                m = mn;
            }

            // refill this buffer with chunk c + 2*NW (K runs, then V runs)
            const int cn = c + 2 * NW;
            if (cn < nch) {
                #pragma unroll
                for (int j = 0; j < CH; ++j) {
                    int i = cn * CH + j;
                    int node = nlist[i < cnt ? i : 0];
                    __pipeline_memcpy_async(buf + j * 256 + loff,
                                            Kb + (size_t)node * STR + cbase, 16);
                }
                #pragma unroll
                for (int j = 0; j < CH; ++j) {
                    int i = cn * CH + j;
                    int node = nlist[i < cnt ? i : 0];
                    __pipeline_memcpy_async(buf + j * 256 + 128 + loff,
                                            Vb + (size_t)node * STR + cbase, 16);
                }
            }
            __pipeline_commit();
        }
        __pipeline_wait_prior(0);
        __syncthreads();   // ring now dead -> reuse as merge scratch

        m_s[wid * 32 + lane] = m;
        l_s[wid * 32 + lane] = lsum;
        a_s[wid * 32 + lane] = acc;
        __syncthreads();

        if (tid < 32) {
            float M = m_s[lane];
            #pragma unroll
            for (int w = 1; w < NW; ++w) M = fmaxf(M, m_s[w * 32 + lane]);
            float L = 0.f, ax = 0.f, ay = 0.f, az = 0.f, aw = 0.f;
            #pragma unroll
            for (int w = 0; w < NW; ++w) {
                const float cc = __expf(m_s[w * 32 + lane] - M);
                L += l_s[w * 32 + lane] * cc;
                const float4 a = a_s[w * 32 + lane];
                ax += a.x * cc; ay += a.y * cc; az += a.z * cc; aw += a.w * cc;
            }
            const float inv = 1.0f / L;
            mo[4 * lane + 0] = ax * inv;
            mo[4 * lane + 1] = ay * inv;
            mo[4 * lane + 2] = az * inv;
            mo[4 * lane + 3] = aw * inv;
        }
        __syncthreads();

        if (tid < D) {   // query = mha_out @ W0_w.T + W0_b
            const float* Wr = W0_w + tid * D;
            float a2 = W0_b[tid];
            #pragma unroll 8
            for (int d = 0; d < D; ++d) a2 = fmaf(mo[d], Wr[d], a2);
            qs[tid] = a2;
        }
        __syncthreads();
    }

    // ==================== Layer 2: q_final = q @ Wq.T + b; 1-head, clip=10 ====================
    if (tid < D) {
        const float* Wr = Wq_w + tid * D;
        float a2 = Wq_b[tid];
        #pragma unroll 8
        for (int d = 0; d < D; ++d) a2 = fmaf(qs[d], Wr[d], a2);
        mo[tid] = a2;
    }
    __syncthreads();

    {
        const int cbase = 2 * D + loff;
        const float4 q4 = *(const float4*)(mo + loff);

        // K-only ring: slot = ring[w][buf][j][0:128]
        #pragma unroll
        for (int d = 0; d < DEPTH; ++d) {
            const int c = wid + d * NW;
            float* buf = rw + d * (CH * 256);
            if (c < nch) {
                #pragma unroll
                for (int j = 0; j < CH; ++j) {
                    int i = c * CH + j;
                    int node = nlist[i < cnt ? i : 0];
                    __pipeline_memcpy_async(buf + j * 256 + loff,
                                            Kb + (size_t)node * STR + cbase, 16);
                }
            }
            __pipeline_commit();
        }

        float m = -1e30f, lsum = 0.0f;
        int it = 0;
        for (int c = wid; c < nch; c += NW, ++it) {
            __pipeline_wait_prior(1);
            float* buf = rw + (it & 1) * (CH * 256);

            #pragma unroll
            for (int j = 0; j < CH; ++j) {
                const int i = c * CH + j;
                const float4 k4 = *(const float4*)(buf + j * 256 + loff);
                float s = k4.x * q4.x + k4.y * q4.y + k4.z * q4.z + k4.w * q4.w;
                #pragma unroll
                for (int d = 1; d < 32; d <<= 1)
                    s += __shfl_xor_sync(0xffffffffu, s, d);
                s *= 0.08838834764831845f;  // 1/sqrt(128)
                s = 10.0f * (1.0f - __fdividef(2.0f, __expf(2.0f * s) + 1.0f));  // 10*tanh
                if (i < cnt) {
                    if (lane == 0) ss[i] = s;   // stage logit in smem
                } else s = NEG;
                const float mn = fmaxf(m, s);
                lsum = lsum * __expf(m - mn) + __expf(s - mn);
                m = mn;
            }

            const int cn = c + 2 * NW;
            if (cn < nch) {
                #pragma unroll
                for (int j = 0; j < CH; ++j) {
                    int i = cn * CH + j;
                    int node = nlist[i < cnt ? i : 0];
                    __pipeline_memcpy_async(buf + j * 256 + loff,
                                            Kb + (size_t)node * STR + cbase, 16);
                }
            }
            __pipeline_commit();
        }
        __pipeline_wait_prior(0);
        __syncthreads();

        if (lane == 0) { m_s[wid * 32] = m; l_s[wid * 32] = lsum; }
        __syncthreads();
        if (tid == 0) {
            float M = m_s[0];
            #pragma unroll
            for (int w = 1; w < NW; ++w) M = fmaxf(M, m_s[w * 32]);
            float L = 0.f;
            #pragma unroll
            for (int w = 0; w < NW; ++w) L += l_s[w * 32] * __expf(m_s[w * 32] - M);
            M2s = M;
            L2s = 1.0f / L;
        }
        __syncthreads();

        // write output: zero everything, then scatter softmax weights from smem
        const float M = M2s, Li = L2s;
        float* orow = out + (size_t)b * NN;
        for (int n = tid; n < NN; n += 256) orow[n] = 0.0f;
        __syncthreads();
        for (int i = tid; i < cnt; i += 256)
            orow[nlist[i]] = __expf(ss[i] - M) * Li;
    }
}

extern "C" void kernel_launch(void* const* d_in, const int* in_sizes, int n_in,
                              void* d_out, int out_size) {
    const float* query = (const float*)d_in[0];
    const float* K_att = (const float*)d_in[1];
    const float* V_att = (const float*)d_in[2];
    const int*   mask  = (const int*)d_in[3];
    const float* W0_w  = (const float*)d_in[4];
    const float* W0_b  = (const float*)d_in[5];
    const float* Wq_w  = (const float*)d_in[6];
    const float* Wq_b  = (const float*)d_in[7];
    float* out = (float*)d_out;

    decoder_fused_kernel<<<512, 256>>>(query, K_att, V_att, mask,
                                       W0_w, W0_b, Wq_w, Wq_b, out);
}